// round 10
// baseline (speedup 1.0000x reference)
#include <cuda_runtime.h>

#define BB 16
#define NN 2048
#define KK 10
#define FULLM 0xffffffffu
#define NCHUNK (NN / 32)          // 64
#define PA 4                      // phase-A chunks (incl. own)

__device__ int      g_idx[BB * NN * KK];
__device__ float    g_loss[BB * NN];
__device__ float4   g_sorted[BB * NN];
__device__ int      g_sidx[BB * NN];
__device__ unsigned g_min[BB];

// ---------------------------------------------------------------------------
// Kernel 0: per-batch bitonic sort of points by x. Also inits g_min.
// ---------------------------------------------------------------------------
__global__ void __launch_bounds__(1024) sort_kernel(const float* __restrict__ src) {
    __shared__ unsigned skey[NN];
    __shared__ int      sval[NN];
    const int b = blockIdx.x;
    const float* base = src + (size_t)b * 3 * NN;
    if (threadIdx.x == 0) g_min[b] = 0x7f800000u;   // +inf bits

    for (int i = threadIdx.x; i < NN; i += 1024) {
        unsigned u = __float_as_uint(base[i]);
        u ^= (u & 0x80000000u) ? 0xFFFFFFFFu : 0x80000000u;  // monotone map
        skey[i] = u; sval[i] = i;
    }

    for (int k = 2; k <= NN; k <<= 1) {
        for (int j = k >> 1; j > 0; j >>= 1) {
            __syncthreads();
            const int t   = threadIdx.x;
            const int i   = 2 * t - (t & (j - 1));
            const int ixj = i + j;
            const bool up = ((i & k) == 0);
            unsigned a = skey[i], c = skey[ixj];
            if ((a > c) == up) {
                skey[i] = c; skey[ixj] = a;
                int v = sval[i]; sval[i] = sval[ixj]; sval[ixj] = v;
            }
        }
    }
    __syncthreads();

    for (int i = threadIdx.x; i < NN; i += 1024) {
        int orig = sval[i];
        float x = base[orig];
        float y = base[NN + orig];
        float z = base[2 * NN + orig];
        g_sorted[b * NN + i] = make_float4(x, y, z, x * x + y * y + z * z);
        g_sidx[b * NN + i]   = orig;
    }
}

// ---------------------------------------------------------------------------
// Kernel 1: warp-per-query masked KNN.
// Own chunk: warp-bitonic full sort -> top-10 + tau. Phase A: 3 more chunks
// (adaptive tau). Phase B: FIXED tau (no loop-carried dep -> unroll/ILP);
// stale tau admits a superset, exact key-insert filters it; extras land in
// lanes >= 10 of the sorted 32-list and are never read.
// Keys (bits(d2+1e-7)<<32)|orig_idx, exact stable top_k.
// ---------------------------------------------------------------------------
#define SCAN_CHUNK(c)                                                         \
    {                                                                         \
        const int i_ = (c) * 32 + lane;                                       \
        float4 p = sp[i_];                                                    \
        float dot = qx * p.x + qy * p.y + qz * p.z;                           \
        float d2f = (qw + p.w - 2.0f * dot) + 1e-7f;                          \
        unsigned du = __float_as_uint(d2f);                                   \
        bool pred = (d2f >= 0.1f) && (du <= tau);                             \
        unsigned m = __ballot_sync(FULLM, pred);                              \
        if (m) {                                                              \
            unsigned long long kk =                                           \
                ((unsigned long long)du << 32) | (unsigned)si[i_];            \
            do {                                                              \
                int s = __ffs(m) - 1;                                         \
                m &= m - 1;                                                   \
                unsigned long long k = __shfl_sync(FULLM, kk, s);             \
                unsigned long long up = __shfl_up_sync(FULLM, key, 1);        \
                bool cc = (k < key);                                          \
                unsigned long long ins = (lane == 0 || up <= k) ? k : up;     \
                key = cc ? ins : key;                                         \
            } while (m);                                                      \
            tau = __shfl_sync(FULLM, (unsigned)(key >> 32), 9);               \
        }                                                                     \
    }

// Fixed-threshold variant: no tau update -> no loop-carried dependency.
#define SCAN_CHUNK_F(c)                                                       \
    {                                                                         \
        const int i_ = (c) * 32 + lane;                                       \
        float4 p = sp[i_];                                                    \
        float dot = qx * p.x + qy * p.y + qz * p.z;                           \
        float d2f = (qw + p.w - 2.0f * dot) + 1e-7f;                          \
        unsigned du = __float_as_uint(d2f);                                   \
        bool pred = (d2f >= 0.1f) && (du <= tauF);                            \
        unsigned m = __ballot_sync(FULLM, pred);                              \
        if (m) {                                                              \
            unsigned long long kk =                                           \
                ((unsigned long long)du << 32) | (unsigned)si[i_];            \
            do {                                                              \
                int s = __ffs(m) - 1;                                         \
                m &= m - 1;                                                   \
                unsigned long long k = __shfl_sync(FULLM, kk, s);             \
                unsigned long long up = __shfl_up_sync(FULLM, key, 1);        \
                bool cc = (k < key);                                          \
                unsigned long long ins = (lane == 0 || up <= k) ? k : up;     \
                key = cc ? ins : key;                                         \
            } while (m);                                                      \
        }                                                                     \
    }

__global__ void __launch_bounds__(512) knn_kernel(const float* __restrict__ src) {
    __shared__ float4 sp[NN];
    __shared__ int    si[NN];
    const int b   = blockIdx.x >> 7;     // 128 blocks per batch, 16 warps each
    const int grp = blockIdx.x & 127;

    for (int i = threadIdx.x; i < NN; i += 512) {
        sp[i] = g_sorted[b * NN + i];
        si[i] = g_sidx[b * NN + i];
    }
    __syncthreads();

    const int warp = threadIdx.x >> 5;
    const int lane = threadIdx.x & 31;
    const int sq   = grp * 16 + warp;    // sorted position of this query
    const int q    = si[sq];             // original index (output row)

    const float4 Q = sp[sq];
    const float qx = Q.x, qy = Q.y, qz = Q.z, qw = Q.w;

    unsigned long long key;
    unsigned tau;
    const int cown = sq >> 5;

    // ---- own chunk: full warp bitonic sort -> top-10 + tau ----
    {
        const int i_ = cown * 32 + lane;
        float4 p = sp[i_];
        float dot = qx * p.x + qy * p.y + qz * p.z;
        float d2f = (qw + p.w - 2.0f * dot) + 1e-7f;
        unsigned du = __float_as_uint(d2f);
        key = (d2f >= 0.1f)
                  ? (((unsigned long long)du << 32) | (unsigned)si[i_])
                  : ~0ULL;
#pragma unroll
        for (int k = 2; k <= 32; k <<= 1) {
#pragma unroll
            for (int j = k >> 1; j > 0; j >>= 1) {
                unsigned long long o = __shfl_xor_sync(FULLM, key, j);
                bool takeMin = (((lane & j) == 0) == ((lane & k) == 0));
                unsigned long long mn = (o < key) ? o : key;
                unsigned long long mx = (o < key) ? key : o;
                key = takeMin ? mn : mx;
            }
        }
        if (lane >= KK) key = ~0ULL;
        tau = __shfl_sync(FULLM, (unsigned)(key >> 32), 9);
    }

    // ---- phase A: 3 more chunks around own (adaptive tau) ----
    int c0 = cown - 1;
    if (c0 < 0) c0 = 0;
    if (c0 > NCHUNK - PA) c0 = NCHUNK - PA;
#pragma unroll
    for (int c = c0; c < c0 + PA; c++) {
        if (c == cown) continue;
        SCAN_CHUNK(c);
    }

    if (tau != 0xFFFFFFFFu) {
        const unsigned tauF = tau;       // frozen threshold for phase B
        // O(1) window bounds from tauF
        const float r = sqrtf(__uint_as_float(tauF) + 1e-4f);
        const float xlo = qx - r, xhi = qx + r;
        bool ov1 = (sp[lane * 32 + 31].x >= xlo) && (sp[lane * 32].x <= xhi);
        bool ov2 = (sp[(lane + 32) * 32 + 31].x >= xlo) &&
                   (sp[(lane + 32) * 32].x <= xhi);
        unsigned m1 = __ballot_sync(FULLM, ov1);
        unsigned m2 = __ballot_sync(FULLM, ov2);
        int clo = m1 ? (__ffs(m1) - 1) : (32 + __ffs(m2) - 1);
        int chi = m2 ? (63 - __clz(m2)) : (31 - __clz(m1));

#pragma unroll 4
        for (int c = clo; c < c0; c++) SCAN_CHUNK_F(c);
#pragma unroll 4
        for (int c = c0 + PA; c <= chi; c++) SCAN_CHUNK_F(c);
    } else {
        // <10 valid so far (rare): scan everything else adaptively
        for (int c = 0; c < NCHUNK; c++) {
            if (c >= c0 && c < c0 + PA) continue;
            SCAN_CHUNK(c);
        }
    }

    int* op = g_idx + ((size_t)(b * NN) + q) * KK;

    unsigned vm = __ballot_sync(FULLM, key != ~0ULL) & 0x3FFu;
    int cnt = __popc(vm);
    if (lane < cnt) op[lane] = (int)(unsigned)key;

    // Very rare: fewer than 10 valid neighbors total -> top_k pads with the
    // smallest masked ORIGINAL indices (all tied at -inf).
    if (cnt < KK && lane == 0) {
        const float* base = src + (size_t)b * 3 * NN;
        int slot = cnt;
        for (int i = 0; i < NN && slot < KK; i++) {
            float x = base[i], y = base[NN + i], z = base[2 * NN + i];
            float pw = x * x + y * y + z * z;
            float dot = qx * x + qy * y + qz * z;
            float d2f = (qw + pw - 2.0f * dot) + 1e-7f;
            if (!(d2f >= 0.1f)) op[slot++] = i;
        }
    }
}

// ---------------------------------------------------------------------------
// Kernel 2: 45 triangle pair losses per point, mean of sqrt of 10 smallest.
// Also reduces the per-batch min into g_min via atomicMin on uint bits.
// ---------------------------------------------------------------------------
__device__ __forceinline__ void sort3(float& a, float& b, float& c) {
    float t0 = fminf(a, b), t1 = fmaxf(a, b);
    float hi = fmaxf(t1, c);
    float mm = fminf(t1, c);
    float lo = fminf(t0, mm);
    float mi = fmaxf(t0, mm);
    a = lo; b = mi; c = hi;
}

#define K2_BLK 256

__global__ void __launch_bounds__(K2_BLK) loss_kernel(const float* __restrict__ src,
                                                      const float* __restrict__ tgt) {
    __shared__ float ssx[NN], ssy[NN], ssz[NN];
    __shared__ float stx[NN], sty[NN], stz[NN];
    const int blocksPerB = NN / K2_BLK;
    const int b     = blockIdx.x / blocksPerB;
    const int chunk = blockIdx.x % blocksPerB;
    const float* sb = src + (size_t)b * 3 * NN;
    const float* tb = tgt + (size_t)b * 3 * NN;

    for (int i = threadIdx.x; i < NN; i += K2_BLK) {
        ssx[i] = sb[i]; ssy[i] = sb[NN + i]; ssz[i] = sb[2 * NN + i];
        stx[i] = tb[i]; sty[i] = tb[NN + i]; stz[i] = tb[2 * NN + i];
    }
    __syncthreads();

    const int n = chunk * K2_BLK + threadIdx.x;
    const int* nb = g_idx + ((size_t)(b * NN) + n) * KK;

    float px[KK + 1], py[KK + 1], pz[KK + 1];
    float tx[KK + 1], ty[KK + 1], tz[KK + 1];
    px[0] = ssx[n]; py[0] = ssy[n]; pz[0] = ssz[n];
    tx[0] = stx[n]; ty[0] = sty[n]; tz[0] = stz[n];
#pragma unroll
    for (int j = 0; j < KK; j++) {
        int m = nb[j];
        px[j + 1] = ssx[m]; py[j + 1] = ssy[m]; pz[j + 1] = ssz[m];
        tx[j + 1] = stx[m]; ty[j + 1] = sty[m]; tz[j + 1] = stz[m];
    }

    const float INF = __int_as_float(0x7f800000);
    float ls[KK];
#pragma unroll
    for (int j = 0; j < KK; j++) ls[j] = INF;
    float worst = INF;

#pragma unroll
    for (int a = 0; a < KK - 1; a++) {
#pragma unroll
        for (int c = a + 1; c < KK; c++) {
            const int ia = a + 1, ic = c + 1;
            float dx, dy, dz;
            dx = px[0] - px[ia]; dy = py[0] - py[ia]; dz = pz[0] - pz[ia];
            float s01 = dx * dx + dy * dy + dz * dz;
            dx = px[ia] - px[ic]; dy = py[ia] - py[ic]; dz = pz[ia] - pz[ic];
            float s12 = dx * dx + dy * dy + dz * dz;
            dx = px[0] - px[ic]; dy = py[0] - py[ic]; dz = pz[0] - pz[ic];
            float s02 = dx * dx + dy * dy + dz * dz;
            sort3(s01, s12, s02);
            dx = tx[0] - tx[ia]; dy = ty[0] - ty[ia]; dz = tz[0] - tz[ia];
            float t01 = dx * dx + dy * dy + dz * dz;
            dx = tx[ia] - tx[ic]; dy = ty[ia] - ty[ic]; dz = tz[ia] - tz[ic];
            float t12 = dx * dx + dy * dy + dz * dz;
            dx = tx[0] - tx[ic]; dy = ty[0] - ty[ic]; dz = tz[0] - tz[ic];
            float t02 = dx * dx + dy * dy + dz * dz;
            sort3(t01, t12, t02);
            t01 += 1e-6f; t12 += 1e-6f; t02 += 1e-6f;

            float n0 = s01 - t01, n1 = s12 - t12, n2 = s02 - t02;
            float num = n0 * n0 + n1 * n1 + n2 * n2;
            float p0 = s01 + t01, p1 = s12 + t12, p2 = s02 + t02;
            float den = p0 * p0 + p1 * p1 + p2 * p2;
            float L = num / den;

            if (L < worst) {
                float cd = L;
#pragma unroll
                for (int j = 0; j < KK; j++) {
                    if (cd < ls[j]) { float t = ls[j]; ls[j] = cd; cd = t; }
                }
                worst = ls[KK - 1];
            }
        }
    }

    float acc = 0.0f;
#pragma unroll
    for (int j = 0; j < KK; j++) acc += sqrtf(ls[j] + 1e-6f);
    float loss = acc * 0.1f;
    g_loss[b * NN + n] = loss;

    // block-level min -> one atomic per warp (nonneg floats: bits are ordered)
    float wm = loss;
#pragma unroll
    for (int o = 16; o; o >>= 1) wm = fminf(wm, __shfl_xor_sync(FULLM, wm, o));
    if ((threadIdx.x & 31) == 0) atomicMin(&g_min[b], __float_as_uint(wm));
}

// ---------------------------------------------------------------------------
// Kernel 3: threshold pass (min already in g_min)
// ---------------------------------------------------------------------------
__global__ void __launch_bounds__(256) weight_kernel(float* __restrict__ out) {
    const int b = blockIdx.x >> 3;           // 8 blocks per batch
    const int i = (blockIdx.x & 7) * 256 + threadIdx.x;
    const float bmin = __uint_as_float(g_min[b]);
    float x = g_loss[b * NN + i] - bmin;
    float w = 2.0f / (1.0f + expf(30.0f * x));
    out[b * NN + i] = (w > 0.6f) ? 1.0f : 0.0f;
}

// ---------------------------------------------------------------------------
extern "C" void kernel_launch(void* const* d_in, const int* in_sizes, int n_in,
                              void* d_out, int out_size) {
    const float* src = (const float*)d_in[0];
    const float* tgt = (const float*)d_in[1];
    float* out = (float*)d_out;

    sort_kernel  <<<BB, 1024>>>(src);
    knn_kernel   <<<BB * (NN / 16), 512>>>(src);
    loss_kernel  <<<BB * (NN / K2_BLK), K2_BLK>>>(src, tgt);
    weight_kernel<<<BB * 8, 256>>>(out);
}

// round 11
// speedup vs baseline: 1.1886x; 1.1886x over previous
#include <cuda_runtime.h>

#define BB 16
#define NN 2048
#define KK 10
#define FULLM 0xffffffffu
#define NCHUNK (NN / 32)          // 64
#define PA 4                      // phase-A chunks (incl. own)
#define QPB 32                    // queries (warps) per knn block

__device__ int      g_idx[BB * NN * KK];
__device__ float    g_loss[BB * NN];
__device__ float4   g_sorted[BB * NN];
__device__ int      g_sidx[BB * NN];
__device__ unsigned g_min[BB];

// ---------------------------------------------------------------------------
// Kernel 0: per-batch bitonic sort of points by x. Also inits g_min.
// ---------------------------------------------------------------------------
__global__ void __launch_bounds__(1024) sort_kernel(const float* __restrict__ src) {
    __shared__ unsigned skey[NN];
    __shared__ int      sval[NN];
    const int b = blockIdx.x;
    const float* base = src + (size_t)b * 3 * NN;
    if (threadIdx.x == 0) g_min[b] = 0x7f800000u;   // +inf bits

    for (int i = threadIdx.x; i < NN; i += 1024) {
        unsigned u = __float_as_uint(base[i]);
        u ^= (u & 0x80000000u) ? 0xFFFFFFFFu : 0x80000000u;  // monotone map
        skey[i] = u; sval[i] = i;
    }

    for (int k = 2; k <= NN; k <<= 1) {
        for (int j = k >> 1; j > 0; j >>= 1) {
            __syncthreads();
            const int t   = threadIdx.x;
            const int i   = 2 * t - (t & (j - 1));
            const int ixj = i + j;
            const bool up = ((i & k) == 0);
            unsigned a = skey[i], c = skey[ixj];
            if ((a > c) == up) {
                skey[i] = c; skey[ixj] = a;
                int v = sval[i]; sval[i] = sval[ixj]; sval[ixj] = v;
            }
        }
    }
    __syncthreads();

    for (int i = threadIdx.x; i < NN; i += 1024) {
        int orig = sval[i];
        float x = base[orig];
        float y = base[NN + orig];
        float z = base[2 * NN + orig];
        g_sorted[b * NN + i] = make_float4(x, y, z, x * x + y * y + z * z);
        g_sidx[b * NN + i]   = orig;
    }
}

// ---------------------------------------------------------------------------
// Kernel 1: warp-per-query masked KNN (adaptive tau everywhere — proven R8).
// Own chunk: warp-bitonic full sort -> top-10 + tau. Phase A: 3 more chunks.
// Window: O(1) ballot chunk-range from tau (d2 >= dx^2, +1e-4 margin).
// Phase B: window loops, adaptive tau (refresh only on insert).
// Keys (bits(d2+1e-7)<<32)|orig_idx, exact stable top_k.
// 32 warps / 32 sorted-adjacent queries per block to halve tile loads.
// ---------------------------------------------------------------------------
#define SCAN_CHUNK(c)                                                         \
    {                                                                         \
        const int i_ = (c) * 32 + lane;                                       \
        float4 p = sp[i_];                                                    \
        float dot = qx * p.x + qy * p.y + qz * p.z;                           \
        float d2f = (qw + p.w - 2.0f * dot) + 1e-7f;                          \
        unsigned du = __float_as_uint(d2f);                                   \
        bool pred = (d2f >= 0.1f) && (du <= tau);                             \
        unsigned m = __ballot_sync(FULLM, pred);                              \
        if (m) {                                                              \
            unsigned long long kk =                                           \
                ((unsigned long long)du << 32) | (unsigned)si[i_];            \
            do {                                                              \
                int s = __ffs(m) - 1;                                         \
                m &= m - 1;                                                   \
                unsigned long long k = __shfl_sync(FULLM, kk, s);             \
                unsigned long long up = __shfl_up_sync(FULLM, key, 1);        \
                bool cc = (k < key);                                          \
                unsigned long long ins = (lane == 0 || up <= k) ? k : up;     \
                key = cc ? ins : key;                                         \
            } while (m);                                                      \
            tau = __shfl_sync(FULLM, (unsigned)(key >> 32), 9);               \
        }                                                                     \
    }

__global__ void __launch_bounds__(1024) knn_kernel(const float* __restrict__ src) {
    __shared__ float4 sp[NN];
    __shared__ int    si[NN];
    const int b   = blockIdx.x >> 6;     // 64 blocks per batch, 32 warps each
    const int grp = blockIdx.x & 63;

    for (int i = threadIdx.x; i < NN; i += 1024) {
        sp[i] = g_sorted[b * NN + i];
        si[i] = g_sidx[b * NN + i];
    }
    __syncthreads();

    const int warp = threadIdx.x >> 5;
    const int lane = threadIdx.x & 31;
    const int sq   = grp * QPB + warp;   // sorted position of this query
    const int q    = si[sq];             // original index (output row)

    const float4 Q = sp[sq];
    const float qx = Q.x, qy = Q.y, qz = Q.z, qw = Q.w;

    unsigned long long key;
    unsigned tau;
    const int cown = sq >> 5;

    // ---- own chunk: full warp bitonic sort -> top-10 + tau ----
    {
        const int i_ = cown * 32 + lane;
        float4 p = sp[i_];
        float dot = qx * p.x + qy * p.y + qz * p.z;
        float d2f = (qw + p.w - 2.0f * dot) + 1e-7f;
        unsigned du = __float_as_uint(d2f);
        key = (d2f >= 0.1f)
                  ? (((unsigned long long)du << 32) | (unsigned)si[i_])
                  : ~0ULL;
#pragma unroll
        for (int k = 2; k <= 32; k <<= 1) {
#pragma unroll
            for (int j = k >> 1; j > 0; j >>= 1) {
                unsigned long long o = __shfl_xor_sync(FULLM, key, j);
                bool takeMin = (((lane & j) == 0) == ((lane & k) == 0));
                unsigned long long mn = (o < key) ? o : key;
                unsigned long long mx = (o < key) ? key : o;
                key = takeMin ? mn : mx;
            }
        }
        if (lane >= KK) key = ~0ULL;
        tau = __shfl_sync(FULLM, (unsigned)(key >> 32), 9);
    }

    // ---- phase A: 3 more chunks around own ----
    int c0 = cown - 1;
    if (c0 < 0) c0 = 0;
    if (c0 > NCHUNK - PA) c0 = NCHUNK - PA;
#pragma unroll
    for (int c = c0; c < c0 + PA; c++) {
        if (c == cown) continue;
        SCAN_CHUNK(c);
    }

    if (tau != 0xFFFFFFFFu) {
        // O(1) window bounds from tau
        const float r = sqrtf(__uint_as_float(tau) + 1e-4f);
        const float xlo = qx - r, xhi = qx + r;
        bool ov1 = (sp[lane * 32 + 31].x >= xlo) && (sp[lane * 32].x <= xhi);
        bool ov2 = (sp[(lane + 32) * 32 + 31].x >= xlo) &&
                   (sp[(lane + 32) * 32].x <= xhi);
        unsigned m1 = __ballot_sync(FULLM, ov1);
        unsigned m2 = __ballot_sync(FULLM, ov2);
        int clo = m1 ? (__ffs(m1) - 1) : (32 + __ffs(m2) - 1);
        int chi = m2 ? (63 - __clz(m2)) : (31 - __clz(m1));

#pragma unroll 2
        for (int c = clo; c < c0; c++) SCAN_CHUNK(c);
#pragma unroll 2
        for (int c = c0 + PA; c <= chi; c++) SCAN_CHUNK(c);
    } else {
        // <10 valid so far (rare): scan everything else
        for (int c = 0; c < NCHUNK; c++) {
            if (c >= c0 && c < c0 + PA) continue;
            SCAN_CHUNK(c);
        }
    }

    int* op = g_idx + ((size_t)(b * NN) + q) * KK;

    unsigned vm = __ballot_sync(FULLM, key != ~0ULL) & 0x3FFu;
    int cnt = __popc(vm);
    if (lane < cnt) op[lane] = (int)(unsigned)key;

    // Very rare: fewer than 10 valid neighbors total -> top_k pads with the
    // smallest masked ORIGINAL indices (all tied at -inf).
    if (cnt < KK && lane == 0) {
        const float* base = src + (size_t)b * 3 * NN;
        int slot = cnt;
        for (int i = 0; i < NN && slot < KK; i++) {
            float x = base[i], y = base[NN + i], z = base[2 * NN + i];
            float pw = x * x + y * y + z * z;
            float dot = qx * x + qy * y + qz * z;
            float d2f = (qw + pw - 2.0f * dot) + 1e-7f;
            if (!(d2f >= 0.1f)) op[slot++] = i;
        }
    }
}

// ---------------------------------------------------------------------------
// Kernel 2: 45 triangle pair losses per point, mean of sqrt of 10 smallest.
// Also reduces the per-batch min into g_min via atomicMin on uint bits.
// ---------------------------------------------------------------------------
__device__ __forceinline__ void sort3(float& a, float& b, float& c) {
    float t0 = fminf(a, b), t1 = fmaxf(a, b);
    float hi = fmaxf(t1, c);
    float mm = fminf(t1, c);
    float lo = fminf(t0, mm);
    float mi = fmaxf(t0, mm);
    a = lo; b = mi; c = hi;
}

#define K2_BLK 256

__global__ void __launch_bounds__(K2_BLK) loss_kernel(const float* __restrict__ src,
                                                      const float* __restrict__ tgt) {
    __shared__ float ssx[NN], ssy[NN], ssz[NN];
    __shared__ float stx[NN], sty[NN], stz[NN];
    const int blocksPerB = NN / K2_BLK;
    const int b     = blockIdx.x / blocksPerB;
    const int chunk = blockIdx.x % blocksPerB;
    const float* sb = src + (size_t)b * 3 * NN;
    const float* tb = tgt + (size_t)b * 3 * NN;

    for (int i = threadIdx.x; i < NN; i += K2_BLK) {
        ssx[i] = sb[i]; ssy[i] = sb[NN + i]; ssz[i] = sb[2 * NN + i];
        stx[i] = tb[i]; sty[i] = tb[NN + i]; stz[i] = tb[2 * NN + i];
    }
    __syncthreads();

    const int n = chunk * K2_BLK + threadIdx.x;
    const int* nb = g_idx + ((size_t)(b * NN) + n) * KK;

    float px[KK + 1], py[KK + 1], pz[KK + 1];
    float tx[KK + 1], ty[KK + 1], tz[KK + 1];
    px[0] = ssx[n]; py[0] = ssy[n]; pz[0] = ssz[n];
    tx[0] = stx[n]; ty[0] = sty[n]; tz[0] = stz[n];
#pragma unroll
    for (int j = 0; j < KK; j++) {
        int m = nb[j];
        px[j + 1] = ssx[m]; py[j + 1] = ssy[m]; pz[j + 1] = ssz[m];
        tx[j + 1] = stx[m]; ty[j + 1] = sty[m]; tz[j + 1] = stz[m];
    }

    const float INF = __int_as_float(0x7f800000);
    float ls[KK];
#pragma unroll
    for (int j = 0; j < KK; j++) ls[j] = INF;
    float worst = INF;

#pragma unroll
    for (int a = 0; a < KK - 1; a++) {
#pragma unroll
        for (int c = a + 1; c < KK; c++) {
            const int ia = a + 1, ic = c + 1;
            float dx, dy, dz;
            dx = px[0] - px[ia]; dy = py[0] - py[ia]; dz = pz[0] - pz[ia];
            float s01 = dx * dx + dy * dy + dz * dz;
            dx = px[ia] - px[ic]; dy = py[ia] - py[ic]; dz = pz[ia] - pz[ic];
            float s12 = dx * dx + dy * dy + dz * dz;
            dx = px[0] - px[ic]; dy = py[0] - py[ic]; dz = pz[0] - pz[ic];
            float s02 = dx * dx + dy * dy + dz * dz;
            sort3(s01, s12, s02);
            dx = tx[0] - tx[ia]; dy = ty[0] - ty[ia]; dz = tz[0] - tz[ia];
            float t01 = dx * dx + dy * dy + dz * dz;
            dx = tx[ia] - tx[ic]; dy = ty[ia] - ty[ic]; dz = tz[ia] - tz[ic];
            float t12 = dx * dx + dy * dy + dz * dz;
            dx = tx[0] - tx[ic]; dy = ty[0] - ty[ic]; dz = tz[0] - tz[ic];
            float t02 = dx * dx + dy * dy + dz * dz;
            sort3(t01, t12, t02);
            t01 += 1e-6f; t12 += 1e-6f; t02 += 1e-6f;

            float n0 = s01 - t01, n1 = s12 - t12, n2 = s02 - t02;
            float num = n0 * n0 + n1 * n1 + n2 * n2;
            float p0 = s01 + t01, p1 = s12 + t12, p2 = s02 + t02;
            float den = p0 * p0 + p1 * p1 + p2 * p2;
            float L = num / den;

            if (L < worst) {
                float cd = L;
#pragma unroll
                for (int j = 0; j < KK; j++) {
                    if (cd < ls[j]) { float t = ls[j]; ls[j] = cd; cd = t; }
                }
                worst = ls[KK - 1];
            }
        }
    }

    float acc = 0.0f;
#pragma unroll
    for (int j = 0; j < KK; j++) acc += sqrtf(ls[j] + 1e-6f);
    float loss = acc * 0.1f;
    g_loss[b * NN + n] = loss;

    // block-level min -> one atomic per warp (nonneg floats: bits are ordered)
    float wm = loss;
#pragma unroll
    for (int o = 16; o; o >>= 1) wm = fminf(wm, __shfl_xor_sync(FULLM, wm, o));
    if ((threadIdx.x & 31) == 0) atomicMin(&g_min[b], __float_as_uint(wm));
}

// ---------------------------------------------------------------------------
// Kernel 3: threshold pass (min already in g_min)
// ---------------------------------------------------------------------------
__global__ void __launch_bounds__(256) weight_kernel(float* __restrict__ out) {
    const int b = blockIdx.x >> 3;           // 8 blocks per batch
    const int i = (blockIdx.x & 7) * 256 + threadIdx.x;
    const float bmin = __uint_as_float(g_min[b]);
    float x = g_loss[b * NN + i] - bmin;
    float w = 2.0f / (1.0f + expf(30.0f * x));
    out[b * NN + i] = (w > 0.6f) ? 1.0f : 0.0f;
}

// ---------------------------------------------------------------------------
extern "C" void kernel_launch(void* const* d_in, const int* in_sizes, int n_in,
                              void* d_out, int out_size) {
    const float* src = (const float*)d_in[0];
    const float* tgt = (const float*)d_in[1];
    float* out = (float*)d_out;

    sort_kernel  <<<BB, 1024>>>(src);
    knn_kernel   <<<BB * (NN / QPB), 1024>>>(src);
    loss_kernel  <<<BB * (NN / K2_BLK), K2_BLK>>>(src, tgt);
    weight_kernel<<<BB * 8, 256>>>(out);
}

// round 12
// speedup vs baseline: 1.2530x; 1.0542x over previous
#include <cuda_runtime.h>

#define BB 16
#define NN 2048
#define KK 10
#define FULLM 0xffffffffu
#define NCHUNK (NN / 32)          // 64

__device__ int      g_idx[BB * NN * KK];
__device__ float    g_loss[BB * NN];
__device__ float4   g_sorted[BB * NN];
__device__ int      g_sidx[BB * NN];
__device__ float4   g_blo[BB * NCHUNK];
__device__ float4   g_bhi[BB * NCHUNK];
__device__ unsigned g_min[BB];

__device__ __forceinline__ unsigned expand10(unsigned v) {
    v &= 1023u;
    v = (v | (v << 16)) & 0x030000FFu;
    v = (v | (v << 8))  & 0x0300F00Fu;
    v = (v | (v << 4))  & 0x030C30C3u;
    v = (v | (v << 2))  & 0x09249249u;
    return v;
}

// ---------------------------------------------------------------------------
// Kernel 0: per-batch bitonic sort of points by MORTON code. Emits sorted
// (x,y,z,|p|^2), original indices, and exact per-chunk AABBs. Inits g_min.
// ---------------------------------------------------------------------------
__global__ void __launch_bounds__(1024) sort_kernel(const float* __restrict__ src) {
    __shared__ unsigned skey[NN];
    __shared__ int      sval[NN];
    __shared__ float    sx[NN], sy[NN], sz[NN];
    const int b = blockIdx.x;
    const float* base = src + (size_t)b * 3 * NN;
    if (threadIdx.x == 0) g_min[b] = 0x7f800000u;   // +inf bits

    for (int i = threadIdx.x; i < NN; i += 1024) {
        float x = base[i], y = base[NN + i], z = base[2 * NN + i];
        int qxi = (int)((x + 8.0f) * 64.0f);
        int qyi = (int)((y + 8.0f) * 64.0f);
        int qzi = (int)((z + 8.0f) * 64.0f);
        qxi = min(max(qxi, 0), 1023);
        qyi = min(max(qyi, 0), 1023);
        qzi = min(max(qzi, 0), 1023);
        skey[i] = (expand10((unsigned)qxi) << 2) |
                  (expand10((unsigned)qyi) << 1) |
                   expand10((unsigned)qzi);
        sval[i] = i;
    }

    for (int k = 2; k <= NN; k <<= 1) {
        for (int j = k >> 1; j > 0; j >>= 1) {
            __syncthreads();
            const int t   = threadIdx.x;
            const int i   = 2 * t - (t & (j - 1));
            const int ixj = i + j;
            const bool up = ((i & k) == 0);
            unsigned a = skey[i], c = skey[ixj];
            if ((a > c) == up) {
                skey[i] = c; skey[ixj] = a;
                int v = sval[i]; sval[i] = sval[ixj]; sval[ixj] = v;
            }
        }
    }
    __syncthreads();

    for (int i = threadIdx.x; i < NN; i += 1024) {
        int orig = sval[i];
        float x = base[orig];
        float y = base[NN + orig];
        float z = base[2 * NN + orig];
        g_sorted[b * NN + i] = make_float4(x, y, z, x * x + y * y + z * z);
        g_sidx[b * NN + i]   = orig;
        sx[i] = x; sy[i] = y; sz[i] = z;
    }
    __syncthreads();

    // exact per-chunk AABBs (32 warps handle 64 chunks)
    const int wid  = threadIdx.x >> 5;
    const int lane = threadIdx.x & 31;
    for (int c = wid; c < NCHUNK; c += 32) {
        float x = sx[c * 32 + lane], y = sy[c * 32 + lane], z = sz[c * 32 + lane];
        float xl = x, xh = x, yl = y, yh = y, zl = z, zh = z;
#pragma unroll
        for (int o = 16; o; o >>= 1) {
            xl = fminf(xl, __shfl_xor_sync(FULLM, xl, o));
            xh = fmaxf(xh, __shfl_xor_sync(FULLM, xh, o));
            yl = fminf(yl, __shfl_xor_sync(FULLM, yl, o));
            yh = fmaxf(yh, __shfl_xor_sync(FULLM, yh, o));
            zl = fminf(zl, __shfl_xor_sync(FULLM, zl, o));
            zh = fmaxf(zh, __shfl_xor_sync(FULLM, zh, o));
        }
        if (lane == 0) {
            g_blo[b * NCHUNK + c] = make_float4(xl, yl, zl, 0.0f);
            g_bhi[b * NCHUNK + c] = make_float4(xh, yh, zh, 0.0f);
        }
    }
}

// ---------------------------------------------------------------------------
// Kernel 1: warp-per-query masked KNN over Morton chunks with AABB pruning.
// Own (Morton-local) chunk: warp-bitonic full sort -> top-10 + TIGHT tau.
// Mask: chunks with exact AABB min-d2 <= tau + 1e-4 (true lower bound of d2;
// margin >> fp error of the d2f formula). Scan masked chunks adaptively.
// Keys (bits(d2+1e-7)<<32)|orig_idx, exact stable top_k.
// ---------------------------------------------------------------------------
#define SCAN_CHUNK(c)                                                         \
    {                                                                         \
        const int i_ = (c) * 32 + lane;                                       \
        float4 p = sp[i_];                                                    \
        float dot = qx * p.x + qy * p.y + qz * p.z;                           \
        float d2f = (qw + p.w - 2.0f * dot) + 1e-7f;                          \
        unsigned du = __float_as_uint(d2f);                                   \
        bool pred = (d2f >= 0.1f) && (du <= tau);                             \
        unsigned m = __ballot_sync(FULLM, pred);                              \
        if (m) {                                                              \
            unsigned long long kk =                                           \
                ((unsigned long long)du << 32) | (unsigned)si[i_];            \
            do {                                                              \
                int s = __ffs(m) - 1;                                         \
                m &= m - 1;                                                   \
                unsigned long long k = __shfl_sync(FULLM, kk, s);             \
                unsigned long long up = __shfl_up_sync(FULLM, key, 1);        \
                bool cc = (k < key);                                          \
                unsigned long long ins = (lane == 0 || up <= k) ? k : up;     \
                key = cc ? ins : key;                                         \
            } while (m);                                                      \
            tau = __shfl_sync(FULLM, (unsigned)(key >> 32), 9);               \
        }                                                                     \
    }

__global__ void __launch_bounds__(512) knn_kernel(const float* __restrict__ src) {
    __shared__ float4 sp[NN];
    __shared__ int    si[NN];
    __shared__ float4 sblo[NCHUNK], sbhi[NCHUNK];
    const int b   = blockIdx.x >> 7;     // 128 blocks per batch, 16 warps each
    const int grp = blockIdx.x & 127;

    for (int i = threadIdx.x; i < NN; i += 512) {
        sp[i] = g_sorted[b * NN + i];
        si[i] = g_sidx[b * NN + i];
    }
    if (threadIdx.x < NCHUNK) {
        sblo[threadIdx.x] = g_blo[b * NCHUNK + threadIdx.x];
        sbhi[threadIdx.x] = g_bhi[b * NCHUNK + threadIdx.x];
    }
    __syncthreads();

    const int warp = threadIdx.x >> 5;
    const int lane = threadIdx.x & 31;
    const int sq   = grp * 16 + warp;    // sorted position of this query
    const int q    = si[sq];             // original index (output row)

    const float4 Q = sp[sq];
    const float qx = Q.x, qy = Q.y, qz = Q.z, qw = Q.w;

    unsigned long long key;
    unsigned tau;
    const int cown = sq >> 5;

    // ---- own (Morton-local) chunk: full warp bitonic sort -> top-10 + tau --
    {
        const int i_ = cown * 32 + lane;
        float4 p = sp[i_];
        float dot = qx * p.x + qy * p.y + qz * p.z;
        float d2f = (qw + p.w - 2.0f * dot) + 1e-7f;
        unsigned du = __float_as_uint(d2f);
        key = (d2f >= 0.1f)
                  ? (((unsigned long long)du << 32) | (unsigned)si[i_])
                  : ~0ULL;
#pragma unroll
        for (int k = 2; k <= 32; k <<= 1) {
#pragma unroll
            for (int j = k >> 1; j > 0; j >>= 1) {
                unsigned long long o = __shfl_xor_sync(FULLM, key, j);
                bool takeMin = (((lane & j) == 0) == ((lane & k) == 0));
                unsigned long long mn = (o < key) ? o : key;
                unsigned long long mx = (o < key) ? key : o;
                key = takeMin ? mn : mx;
            }
        }
        if (lane >= KK) key = ~0ULL;
        tau = __shfl_sync(FULLM, (unsigned)(key >> 32), 9);
    }

    // ---- AABB mask: chunks that can still contain a better neighbor ----
    const float INF = __int_as_float(0x7f800000);
    const float lim = ((tau == 0xFFFFFFFFu) ? INF : __uint_as_float(tau)) + 1e-4f;

    float md[2];
#pragma unroll
    for (int h = 0; h < 2; h++) {
        const int c = lane + h * 32;
        float4 lo = sblo[c], hi = sbhi[c];
        float dx = fmaxf(0.0f, fmaxf(lo.x - qx, qx - hi.x));
        float dy = fmaxf(0.0f, fmaxf(lo.y - qy, qy - hi.y));
        float dz = fmaxf(0.0f, fmaxf(lo.z - qz, qz - hi.z));
        md[h] = dx * dx + dy * dy + dz * dz;
    }
    unsigned m1 = __ballot_sync(FULLM, md[0] <= lim);
    unsigned m2 = __ballot_sync(FULLM, md[1] <= lim);
    if (cown < 32) m1 &= ~(1u << cown); else m2 &= ~(1u << (cown - 32));

    while (m1) {
        int c = __ffs(m1) - 1;
        m1 &= m1 - 1;
        SCAN_CHUNK(c);
    }
    while (m2) {
        int c = 32 + __ffs(m2) - 1;
        m2 &= m2 - 1;
        SCAN_CHUNK(c);
    }

    int* op = g_idx + ((size_t)(b * NN) + q) * KK;

    unsigned vm = __ballot_sync(FULLM, key != ~0ULL) & 0x3FFu;
    int cnt = __popc(vm);
    if (lane < cnt) op[lane] = (int)(unsigned)key;

    // Very rare: fewer than 10 valid neighbors total -> top_k pads with the
    // smallest masked ORIGINAL indices (all tied at -inf).
    if (cnt < KK && lane == 0) {
        const float* base = src + (size_t)b * 3 * NN;
        int slot = cnt;
        for (int i = 0; i < NN && slot < KK; i++) {
            float x = base[i], y = base[NN + i], z = base[2 * NN + i];
            float pw = x * x + y * y + z * z;
            float dot = qx * x + qy * y + qz * z;
            float d2f = (qw + pw - 2.0f * dot) + 1e-7f;
            if (!(d2f >= 0.1f)) op[slot++] = i;
        }
    }
}

// ---------------------------------------------------------------------------
// Kernel 2: 45 triangle pair losses per point, mean of sqrt of 10 smallest.
// Also reduces the per-batch min into g_min via atomicMin on uint bits.
// ---------------------------------------------------------------------------
__device__ __forceinline__ void sort3(float& a, float& b, float& c) {
    float t0 = fminf(a, b), t1 = fmaxf(a, b);
    float hi = fmaxf(t1, c);
    float mm = fminf(t1, c);
    float lo = fminf(t0, mm);
    float mi = fmaxf(t0, mm);
    a = lo; b = mi; c = hi;
}

#define K2_BLK 256

__global__ void __launch_bounds__(K2_BLK) loss_kernel(const float* __restrict__ src,
                                                      const float* __restrict__ tgt) {
    __shared__ float ssx[NN], ssy[NN], ssz[NN];
    __shared__ float stx[NN], sty[NN], stz[NN];
    const int blocksPerB = NN / K2_BLK;
    const int b     = blockIdx.x / blocksPerB;
    const int chunk = blockIdx.x % blocksPerB;
    const float* sb = src + (size_t)b * 3 * NN;
    const float* tb = tgt + (size_t)b * 3 * NN;

    for (int i = threadIdx.x; i < NN; i += K2_BLK) {
        ssx[i] = sb[i]; ssy[i] = sb[NN + i]; ssz[i] = sb[2 * NN + i];
        stx[i] = tb[i]; sty[i] = tb[NN + i]; stz[i] = tb[2 * NN + i];
    }
    __syncthreads();

    const int n = chunk * K2_BLK + threadIdx.x;
    const int* nb = g_idx + ((size_t)(b * NN) + n) * KK;

    float px[KK + 1], py[KK + 1], pz[KK + 1];
    float tx[KK + 1], ty[KK + 1], tz[KK + 1];
    px[0] = ssx[n]; py[0] = ssy[n]; pz[0] = ssz[n];
    tx[0] = stx[n]; ty[0] = sty[n]; tz[0] = stz[n];
#pragma unroll
    for (int j = 0; j < KK; j++) {
        int m = nb[j];
        px[j + 1] = ssx[m]; py[j + 1] = ssy[m]; pz[j + 1] = ssz[m];
        tx[j + 1] = stx[m]; ty[j + 1] = sty[m]; tz[j + 1] = stz[m];
    }

    const float INF = __int_as_float(0x7f800000);
    float ls[KK];
#pragma unroll
    for (int j = 0; j < KK; j++) ls[j] = INF;
    float worst = INF;

#pragma unroll
    for (int a = 0; a < KK - 1; a++) {
#pragma unroll
        for (int c = a + 1; c < KK; c++) {
            const int ia = a + 1, ic = c + 1;
            float dx, dy, dz;
            dx = px[0] - px[ia]; dy = py[0] - py[ia]; dz = pz[0] - pz[ia];
            float s01 = dx * dx + dy * dy + dz * dz;
            dx = px[ia] - px[ic]; dy = py[ia] - py[ic]; dz = pz[ia] - pz[ic];
            float s12 = dx * dx + dy * dy + dz * dz;
            dx = px[0] - px[ic]; dy = py[0] - py[ic]; dz = pz[0] - pz[ic];
            float s02 = dx * dx + dy * dy + dz * dz;
            sort3(s01, s12, s02);
            dx = tx[0] - tx[ia]; dy = ty[0] - ty[ia]; dz = tz[0] - tz[ia];
            float t01 = dx * dx + dy * dy + dz * dz;
            dx = tx[ia] - tx[ic]; dy = ty[ia] - ty[ic]; dz = tz[ia] - tz[ic];
            float t12 = dx * dx + dy * dy + dz * dz;
            dx = tx[0] - tx[ic]; dy = ty[0] - ty[ic]; dz = tz[0] - tz[ic];
            float t02 = dx * dx + dy * dy + dz * dz;
            sort3(t01, t12, t02);
            t01 += 1e-6f; t12 += 1e-6f; t02 += 1e-6f;

            float n0 = s01 - t01, n1 = s12 - t12, n2 = s02 - t02;
            float num = n0 * n0 + n1 * n1 + n2 * n2;
            float p0 = s01 + t01, p1 = s12 + t12, p2 = s02 + t02;
            float den = p0 * p0 + p1 * p1 + p2 * p2;
            float L = num / den;

            if (L < worst) {
                float cd = L;
#pragma unroll
                for (int j = 0; j < KK; j++) {
                    if (cd < ls[j]) { float t = ls[j]; ls[j] = cd; cd = t; }
                }
                worst = ls[KK - 1];
            }
        }
    }

    float acc = 0.0f;
#pragma unroll
    for (int j = 0; j < KK; j++) acc += sqrtf(ls[j] + 1e-6f);
    float loss = acc * 0.1f;
    g_loss[b * NN + n] = loss;

    // block-level min -> one atomic per warp (nonneg floats: bits are ordered)
    float wm = loss;
#pragma unroll
    for (int o = 16; o; o >>= 1) wm = fminf(wm, __shfl_xor_sync(FULLM, wm, o));
    if ((threadIdx.x & 31) == 0) atomicMin(&g_min[b], __float_as_uint(wm));
}

// ---------------------------------------------------------------------------
// Kernel 3: threshold pass (min already in g_min)
// ---------------------------------------------------------------------------
__global__ void __launch_bounds__(256) weight_kernel(float* __restrict__ out) {
    const int b = blockIdx.x >> 3;           // 8 blocks per batch
    const int i = (blockIdx.x & 7) * 256 + threadIdx.x;
    const float bmin = __uint_as_float(g_min[b]);
    float x = g_loss[b * NN + i] - bmin;
    float w = 2.0f / (1.0f + expf(30.0f * x));
    out[b * NN + i] = (w > 0.6f) ? 1.0f : 0.0f;
}

// ---------------------------------------------------------------------------
extern "C" void kernel_launch(void* const* d_in, const int* in_sizes, int n_in,
                              void* d_out, int out_size) {
    const float* src = (const float*)d_in[0];
    const float* tgt = (const float*)d_in[1];
    float* out = (float*)d_out;

    sort_kernel  <<<BB, 1024>>>(src);
    knn_kernel   <<<BB * (NN / 16), 512>>>(src);
    loss_kernel  <<<BB * (NN / K2_BLK), K2_BLK>>>(src, tgt);
    weight_kernel<<<BB * 8, 256>>>(out);
}